// round 17
// baseline (speedup 1.0000x reference)
#include <cuda_runtime.h>

#define TT 512
#define DIN 64
#define HH 128
#define G3 384

typedef unsigned long long u64;

// ---------- packed f32x2 helpers (halves = adjacent k) ----------
__device__ __forceinline__ u64 f2fma(u64 a, u64 b, u64 c) {
    u64 d; asm("fma.rn.f32x2 %0, %1, %2, %3;" : "=l"(d) : "l"(a), "l"(b), "l"(c)); return d;
}
__device__ __forceinline__ u64 f2add(u64 a, u64 b) {
    u64 d; asm("add.rn.f32x2 %0, %1, %2;" : "=l"(d) : "l"(a), "l"(b)); return d;
}
__device__ __forceinline__ float f2red(u64 v) {
    float lo, hi; asm("mov.b64 {%0, %1}, %2;" : "=f"(lo), "=f"(hi) : "l"(v)); return lo + hi;
}
__device__ __forceinline__ u64 pack2f(float x, float y) {
    u64 d; asm("mov.b64 %0, {%1, %2};" : "=l"(d) : "f"(x), "f"(y)); return d;
}
__device__ __forceinline__ float2 unpack2(u64 v) {
    float2 r; asm("mov.b64 {%0, %1}, %2;" : "=f"(r.x), "=f"(r.y) : "l"(v)); return r;
}
__device__ __forceinline__ float tanh_mufu(float x) {
    float y; asm("tanh.approx.f32 %0, %1;" : "=f"(y) : "f"(x)); return y;
}
__device__ __forceinline__ float sigm(float x) {
    return __fdividef(1.0f, 1.0f + __expf(-x));
}

// ---------- device scratch ----------
__device__ float d_Whh_q[HH * G3];     // quad-interleaved: [(k>>2)][o][k&3]
__device__ float d_dts[TT];
__device__ unsigned char d_mask[TT];

// ---------- prologue ----------
__global__ void prep_kernel(const float* __restrict__ W_hh,
                            const float* __restrict__ tp,
                            const unsigned char* __restrict__ mask_raw)
{
    int i = blockIdx.x * blockDim.x + threadIdx.x;
    if (i < HH * G3) { int o = i / HH, k = i % HH;
        d_Whh_q[(k >> 2) * (G3 * 4) + o * 4 + (k & 3)] = W_hh[i]; }
    if (i < TT) d_dts[i] = (i == 0) ? 0.01f : (tp[i] - tp[i - 1]);

    // mask dtype sniffing (uint8 vs int32/float32 marshalling)
    if (blockIdx.x == 0) {
        __shared__ int s_off4, s_f32;
        if (threadIdx.x == 0) { s_off4 = 0; s_f32 = 0; }
        __syncthreads();
        for (int k = threadIdx.x; k < TT; k += blockDim.x)
            if (mask_raw[k] != 0 && (k & 3) != 0) atomicOr(&s_off4, 1);
        for (int k = threadIdx.x; k < TT / 4; k += blockDim.x)
            if (mask_raw[4 * k + 3] == 0x3f) atomicOr(&s_f32, 1);
        __syncthreads();
        bool word = (s_off4 == 0) || (s_f32 != 0);
        const int* mi = (const int*)mask_raw;
        for (int k = threadIdx.x; k < TT; k += blockDim.x)
            d_mask[k] = word ? (unsigned char)(mi[k] != 0)
                             : (unsigned char)(mask_raw[k] != 0);
    }
}

// ---------- smem layout (bytes) ----------
#define OFF_WHH   0        // 196608 : W_hh quads
#define OFF_SCG   196608   // 16384  : GRU packed partials RZ[2][512]u64 + IN[2][512]u64
#define OFF_H     212992   // 1024   : h     [2][128]
#define OFF_HODE  214016   // 1024   : h_ode [2][128]
#define OFF_INP   215040   // 512    : inp   [2][64]
#define OFF_DTS   215552   // 2048
#define OFF_MASK  217600   // 512
#define SMEM_BYTES 218112

__global__ __launch_bounds__(512, 1)
void gruode_kernel(const float* __restrict__ x,
                   const float* __restrict__ W_ih,
                   const float* __restrict__ b_ih,
                   const float* __restrict__ b_hh,
                   const float* __restrict__ W_node,
                   const float* __restrict__ b_node,
                   const float* __restrict__ W_out,
                   const float* __restrict__ b_out,
                   float* __restrict__ out)
{
    extern __shared__ char smem[];
    float* Whh_s   = (float*)(smem + OFF_WHH);
    u64*   scgRZ   = (u64*)(smem + OFF_SCG);            // [2][512] packed (r,z)
    u64*   scgIN   = (u64*)(smem + OFF_SCG + 8192);     // [2][512] packed (i,n)
    float* h_sm    = (float*)(smem + OFF_H);
    float* hode_sm = (float*)(smem + OFF_HODE);
    float* inp_sm  = (float*)(smem + OFF_INP);
    float* sdts    = (float*)(smem + OFF_DTS);
    unsigned char* smask = (unsigned char*)(smem + OFF_MASK);

    const int t   = threadIdx.x;
    const int bid = blockIdx.x;
    // GRU mapping (phases B/C)
    const int c4  = t >> 7;        // warp-uniform k-chunk
    const int j   = t & 127;
    // mv-shfl mapping (phase A)
    const int j4  = t >> 2;        // output row
    const int c4l = t & 3;         // lane k-chunk
    const int sWm = c4l >> 1;      // writer sample
    const bool iswm = (c4l & 1) == 0;
    // outproj-shfl mapping (phase A)
    const int oo8 = t >> 3;        // output col
    const int cl  = t & 7;         // lane k-chunk
    const int sWo = cl >> 2;
    const bool iswo = (cl & 3) == 0;

    // ---- stage W_hh into smem ----
    {
        const float4* src = (const float4*)d_Whh_q;
        float4* dst = (float4*)Whh_s;
        #pragma unroll
        for (int i = 0; i < 24; i++) dst[t + 512 * i] = src[t + 512 * i];
    }
    for (int i = t; i < TT; i += 512) { sdts[i] = d_dts[i]; smask[i] = d_mask[i]; }

    // ---- register weights (k-pair packed, natural loads) ----
    u64 wn2[16];                                   // W_node[j4][32*c4l .. +32)
    {
        const u64* p = (const u64*)(W_node + j4 * HH + 32 * c4l);
        #pragma unroll
        for (int i = 0; i < 16; i++) wn2[i] = p[i];
    }
    u64 wihr[8], wihz[8], wihn[8];                 // W_ih rows j,128+j,256+j ; k in [16c4,+16)
    {
        const u64* pr = (const u64*)(W_ih + (j)        * DIN + 16 * c4);
        const u64* pz = (const u64*)(W_ih + (HH + j)   * DIN + 16 * c4);
        const u64* pn = (const u64*)(W_ih + (2*HH + j) * DIN + 16 * c4);
        #pragma unroll
        for (int i = 0; i < 8; i++) { wihr[i] = pr[i]; wihz[i] = pz[i]; wihn[i] = pn[i]; }
    }
    u64 wout2[8];                                  // W_out[oo8][16*cl .. +16)
    {
        const u64* p = (const u64*)(W_out + oo8 * HH + 16 * cl);
        #pragma unroll
        for (int i = 0; i < 8; i++) wout2[i] = p[i];
    }

    // ---- per-thread biases / state ----
    const float bn = b_node[j4];                   // Euler (mv writer lanes)
    float br = 0.f, bz = 0.f, bin = 0.f, bhn = 0.f;
    if (t < 256) {
        br  = b_ih[j] + b_hh[j];
        bz  = b_ih[HH + j] + b_hh[HH + j];
        bin = b_ih[2*HH + j];
        bhn = b_hh[2*HH + j];
    }
    const float bout = b_out[oo8];                 // outproj writer lanes
    float xreg = 0.f;
    if (t < 256) h_sm[t] = 0.f;                    // h0 = 0
    __syncthreads();

    // step-0 input: mask[0] ? x[0] : out(h0)=b_out ; prefetch x[1]
    if (t < 128) {
        int s = t >> 6, oo = t & 63;
        inp_sm[t] = (smask[0] != 0) ? x[((2 * bid + s) * TT) * DIN + oo]
                                    : b_out[oo];
        xreg = x[((2 * bid + s) * TT + 1) * DIN + oo];
    }
    __syncthreads();

    for (int st = 0; st < TT; st++) {
        const float dt = sdts[st];

        // ================= Phase A =================
        // (1) node matvec, 4-lane shfl butterfly -> Euler -> hode_sm
        {
            const ulonglong2* q0 = (const ulonglong2*)(h_sm)      + 8 * c4l;
            const ulonglong2* q1 = (const ulonglong2*)(h_sm + HH) + 8 * c4l;
            u64 a0 = 0, a1 = 0, b0 = 0, b1 = 0;
            #pragma unroll
            for (int p = 0; p < 8; p++) {
                ulonglong2 v0 = q0[p], v1 = q1[p];
                a0 = f2fma(wn2[2*p],   v0.x, a0);
                a1 = f2fma(wn2[2*p+1], v0.y, a1);
                b0 = f2fma(wn2[2*p],   v1.x, b0);
                b1 = f2fma(wn2[2*p+1], v1.y, b1);
            }
            float d0 = f2red(f2add(a0, a1));
            float d1 = f2red(f2add(b0, b1));
            d0 += __shfl_xor_sync(0xFFFFFFFFu, d0, 1);
            d0 += __shfl_xor_sync(0xFFFFFFFFu, d0, 2);
            d1 += __shfl_xor_sync(0xFFFFFFFFu, d1, 1);
            d1 += __shfl_xor_sync(0xFFFFFFFFu, d1, 2);
            if (iswm) {
                float hv = h_sm[sWm * HH + j4];
                float ds = sWm ? d1 : d0;
                hode_sm[sWm * HH + j4] = hv + dt * tanh_mufu(ds + bn);
            }
        }
        // (2) out-projection of H_{st-1}, 8-lane butterfly -> gmem + teacher-forcing inp
        if (st) {
            const ulonglong2* hp0 = (const ulonglong2*)(h_sm)      + 4 * cl;
            const ulonglong2* hp1 = (const ulonglong2*)(h_sm + HH) + 4 * cl;
            u64 a0 = 0, a1 = 0, b0 = 0, b1 = 0;
            #pragma unroll
            for (int p = 0; p < 4; p++) {
                ulonglong2 v = hp0[p], w = hp1[p];
                a0 = f2fma(wout2[2*p],   v.x, a0);
                a1 = f2fma(wout2[2*p+1], v.y, a1);
                b0 = f2fma(wout2[2*p],   w.x, b0);
                b1 = f2fma(wout2[2*p+1], w.y, b1);
            }
            float o0 = f2red(f2add(a0, a1));
            float o1 = f2red(f2add(b0, b1));
            #pragma unroll
            for (int m = 1; m <= 4; m <<= 1) {
                o0 += __shfl_xor_sync(0xFFFFFFFFu, o0, m);
                o1 += __shfl_xor_sync(0xFFFFFFFFu, o1, m);
            }
            if (iswo) {
                float v = (sWo ? o1 : o0) + bout;
                out[((2 * bid + sWo) * TT + st - 1) * DIN + oo8] = v;
                if (smask[st] == 0) inp_sm[sWo * DIN + oo8] = v;
            }
        }
        // (3) sampled-step input + x prefetch
        if (t < 128) {
            int s = t >> 6, oo = t & 63;
            if (st && smask[st] != 0) inp_sm[s * DIN + oo] = xreg;
            if (st + 1 < TT)
                xreg = x[((2 * bid + s) * TT + st + 1) * DIN + oo];
        }
        __syncthreads();

        // ================= Phase B: GRU gate partials (dual-sample) =================
        {
            const ulonglong2* W2  = (const ulonglong2*)Whh_s;
            const ulonglong2* hq0 = (const ulonglong2*)(hode_sm)      + 8 * c4;
            const ulonglong2* hq1 = (const ulonglong2*)(hode_sm + HH) + 8 * c4;
            u64 r0=0, z0=0, n0=0, r1=0, z1=0, n1=0;
            #pragma unroll
            for (int qq = 0; qq < 8; qq++) {
                int b = (8 * c4 + qq) * G3;
                ulonglong2 wr = W2[b + j];
                ulonglong2 wz = W2[b + HH + j];
                ulonglong2 wn = W2[b + 2*HH + j];
                ulonglong2 h0 = hq0[qq], h1 = hq1[qq];
                r0 = f2fma(wr.x, h0.x, r0); r0 = f2fma(wr.y, h0.y, r0);
                z0 = f2fma(wz.x, h0.x, z0); z0 = f2fma(wz.y, h0.y, z0);
                n0 = f2fma(wn.x, h0.x, n0); n0 = f2fma(wn.y, h0.y, n0);
                r1 = f2fma(wr.x, h1.x, r1); r1 = f2fma(wr.y, h1.y, r1);
                z1 = f2fma(wz.x, h1.x, z1); z1 = f2fma(wz.y, h1.y, z1);
                n1 = f2fma(wn.x, h1.x, n1); n1 = f2fma(wn.y, h1.y, n1);
            }
            const u64* in0 = (const u64*)(inp_sm)       + 8 * c4;
            const u64* in1 = (const u64*)(inp_sm + DIN) + 8 * c4;
            u64 i0 = 0, i1 = 0;
            #pragma unroll
            for (int p = 0; p < 8; p++) {
                u64 a = in0[p], b = in1[p];
                r0 = f2fma(wihr[p], a, r0);
                z0 = f2fma(wihz[p], a, z0);
                i0 = f2fma(wihn[p], a, i0);
                r1 = f2fma(wihr[p], b, r1);
                z1 = f2fma(wihz[p], b, z1);
                i1 = f2fma(wihn[p], b, i1);
            }
            int o = c4 * HH + j;
            scgRZ[      o] = pack2f(f2red(r0), f2red(z0));
            scgRZ[512 + o] = pack2f(f2red(r1), f2red(z1));
            scgIN[      o] = pack2f(f2red(i0), f2red(n0));
            scgIN[512 + o] = pack2f(f2red(i1), f2red(n1));
        }
        __syncthreads();

        // ================= Phase C: GRU combine -> h_sm = H_st =================
        if (t < 256) {
            const int sC = t >> 7, jC = t & 127;
            const u64* bz_ = scgRZ + sC * 512 + jC;
            const u64* bi_ = scgIN + sC * 512 + jC;
            u64 rz   = f2add(f2add(bz_[0], bz_[128]), f2add(bz_[256], bz_[384]));
            u64 sin_ = f2add(f2add(bi_[0], bi_[128]), f2add(bi_[256], bi_[384]));
            float2 g = unpack2(rz);
            float2 w = unpack2(sin_);
            float r = sigm(g.x + br);
            float z = sigm(g.y + bz);
            float n = tanhf(w.x + bin + r * (w.y + bhn));
            float ho = hode_sm[sC * HH + jC];
            h_sm[sC * HH + jC] = (1.f - z) * n + z * ho;
        }
        __syncthreads();
    }

    // ---- epilogue: out[511] from H_511 (outproj-shfl) ----
    {
        const ulonglong2* hp0 = (const ulonglong2*)(h_sm)      + 4 * cl;
        const ulonglong2* hp1 = (const ulonglong2*)(h_sm + HH) + 4 * cl;
        u64 a0 = 0, a1 = 0, b0 = 0, b1 = 0;
        #pragma unroll
        for (int p = 0; p < 4; p++) {
            ulonglong2 v = hp0[p], w = hp1[p];
            a0 = f2fma(wout2[2*p],   v.x, a0);
            a1 = f2fma(wout2[2*p+1], v.y, a1);
            b0 = f2fma(wout2[2*p],   w.x, b0);
            b1 = f2fma(wout2[2*p+1], w.y, b1);
        }
        float o0 = f2red(f2add(a0, a1));
        float o1 = f2red(f2add(b0, b1));
        #pragma unroll
        for (int m = 1; m <= 4; m <<= 1) {
            o0 += __shfl_xor_sync(0xFFFFFFFFu, o0, m);
            o1 += __shfl_xor_sync(0xFFFFFFFFu, o1, m);
        }
        if (iswo) {
            float v = (sWo ? o1 : o0) + bout;
            out[((2 * bid + sWo) * TT + TT - 1) * DIN + oo8] = v;
        }
    }
}

extern "C" void kernel_launch(void* const* d_in, const int* in_sizes, int n_in,
                              void* d_out, int out_size)
{
    (void)in_sizes; (void)n_in; (void)out_size;
    const float* x       = (const float*)d_in[0];
    const float* tp      = (const float*)d_in[1];
    const unsigned char* mask = (const unsigned char*)d_in[2];
    const float* W_ih    = (const float*)d_in[3];
    const float* W_hh    = (const float*)d_in[4];
    const float* b_ih    = (const float*)d_in[5];
    const float* b_hh    = (const float*)d_in[6];
    const float* W_node  = (const float*)d_in[7];
    const float* b_node  = (const float*)d_in[8];
    const float* W_out   = (const float*)d_in[9];
    const float* b_out   = (const float*)d_in[10];
    float* out = (float*)d_out;

    prep_kernel<<<192, 256>>>(W_hh, tp, mask);

    cudaFuncSetAttribute(gruode_kernel,
                         cudaFuncAttributeMaxDynamicSharedMemorySize, SMEM_BYTES);
    gruode_kernel<<<128, 512, SMEM_BYTES>>>(x, W_ih, b_ih, b_hh, W_node, b_node,
                                            W_out, b_out, out);
}